// round 4
// baseline (speedup 1.0000x reference)
#include <cuda_runtime.h>
#include <cuda_bf16.h>
#include <cstdint>

// Problem constants (fixed by dataset)
#define DFEAT 512
#define NOUT  64
#define MAXN  100032          // N_NODES rounded up to 64
#define NPAD  102400          // node arrays padded to 1024*100 for scan tiles
#define MAXE  1600000
#define NBLK_SCAN 100         // NPAD / 1024

// Static device scratch (no runtime allocation allowed)
__device__ float g_h[(size_t)MAXN * NOUT];     // projected features  (25.6 MB)
__device__ uint2 g_pairs[MAXE];                 // (src, w-bits) grouped by dst (12.8 MB)
__device__ int   g_cnt[NPAD];                   // per-dst degree
__device__ int   g_start[NPAD];                 // CSR row start
__device__ int   g_cursor[NPAD];                // fill cursor; == row end after reorder
__device__ int   g_bsum[NBLK_SCAN];             // scan block partials

// ---------------------------------------------------------------------------
// CSR build step 1: zero the degree histogram (padded region included)
// ---------------------------------------------------------------------------
__global__ void zero_cnt_kernel() {
    int i = blockIdx.x * blockDim.x + threadIdx.x;
    if (i < NPAD / 4) ((int4*)g_cnt)[i] = make_int4(0, 0, 0, 0);
}

// ---------------------------------------------------------------------------
// CSR build step 2: degree histogram over dst
// ---------------------------------------------------------------------------
__global__ void hist_kernel(const int* __restrict__ edst, int n_edges) {
    int e = blockIdx.x * blockDim.x + threadIdx.x;
    if (e < n_edges) atomicAdd(&g_cnt[__ldg(&edst[e])], 1);   // -> REDG
}

// ---------------------------------------------------------------------------
// CSR build step 3a: per-tile (1024 nodes) sums
// ---------------------------------------------------------------------------
__global__ void __launch_bounds__(256) scan_reduce_kernel() {
    int idx = blockIdx.x * 1024 + threadIdx.x * 4;
    int4 c = *(const int4*)&g_cnt[idx];
    int s = c.x + c.y + c.z + c.w;
#pragma unroll
    for (int o = 16; o > 0; o >>= 1) s += __shfl_xor_sync(0xffffffffu, s, o);
    __shared__ int ws_[8];
    if ((threadIdx.x & 31) == 0) ws_[threadIdx.x >> 5] = s;
    __syncthreads();
    if (threadIdx.x == 0) {
        int t = 0;
#pragma unroll
        for (int i = 0; i < 8; ++i) t += ws_[i];
        g_bsum[blockIdx.x] = t;
    }
}

// ---------------------------------------------------------------------------
// CSR build step 3b: exclusive scan of the tile sums (single block)
// ---------------------------------------------------------------------------
__global__ void __launch_bounds__(128) scan_mid_kernel(int nb) {
    int tid = threadIdx.x;
    int v = (tid < nb) ? g_bsum[tid] : 0;
    int incl = v;
#pragma unroll
    for (int o = 1; o < 32; o <<= 1) {
        int u = __shfl_up_sync(0xffffffffu, incl, o);
        if ((tid & 31) >= o) incl += u;
    }
    __shared__ int wsum[4];
    if ((tid & 31) == 31) wsum[tid >> 5] = incl;
    __syncthreads();
    int w = tid >> 5, off = 0;
    if (w > 0) off += wsum[0];
    if (w > 1) off += wsum[1];
    if (w > 2) off += wsum[2];
    int excl = incl - v + off;
    if (tid < nb) g_bsum[tid] = excl;
}

// ---------------------------------------------------------------------------
// CSR build step 3c: full exclusive scan -> g_start, and init g_cursor
// ---------------------------------------------------------------------------
__global__ void __launch_bounds__(256) scan_scatter_kernel() {
    int idx = blockIdx.x * 1024 + threadIdx.x * 4;
    int4 c = *(const int4*)&g_cnt[idx];
    int t = c.x + c.y + c.z + c.w;
    int incl = t;
#pragma unroll
    for (int o = 1; o < 32; o <<= 1) {
        int u = __shfl_up_sync(0xffffffffu, incl, o);
        if ((threadIdx.x & 31) >= o) incl += u;
    }
    __shared__ int wsum[8];
    if ((threadIdx.x & 31) == 31) wsum[threadIdx.x >> 5] = incl;
    __syncthreads();
    int wid = threadIdx.x >> 5, off = 0;
#pragma unroll
    for (int i = 0; i < 8; ++i) if (i < wid) off += wsum[i];
    int s0 = incl - t + off + g_bsum[blockIdx.x];
    int4 st;
    st.x = s0; st.y = s0 + c.x; st.z = st.y + c.y; st.w = st.z + c.z;
    *(int4*)&g_start[idx]  = st;
    *(int4*)&g_cursor[idx] = st;
}

// ---------------------------------------------------------------------------
// CSR build step 4: reorder edges into dst-grouped (src, w) pairs.
// After this, g_cursor[d] == row end for node d.
// ---------------------------------------------------------------------------
__global__ void __launch_bounds__(256) reorder_kernel(const int*   __restrict__ esrc,
                                                      const int*   __restrict__ edst,
                                                      const float* __restrict__ ew,
                                                      int n_edges)
{
    int e = blockIdx.x * blockDim.x + threadIdx.x;
    if (e >= n_edges) return;
    int d = __ldg(&edst[e]);
    int pos = atomicAdd(&g_cursor[d], 1);
    g_pairs[pos] = make_uint2((unsigned)__ldg(&esrc[e]), __float_as_uint(__ldg(&ew[e])));
}

// ---------------------------------------------------------------------------
// GEMM: h = x @ W   [N,512] x [512,64] -> [N,64], fp32 packed FFMA2.
// Tile 64x64, BK=16, 256 threads, 4x4 per-thread block.
// x tile stored k-major AND value-duplicated (xs_dup[k][2r]=xs_dup[k][2r+1]=x)
// so the a-operand is ready-packed f32x2 and no mov.b64 duplication is needed.
// Row pad 130 makes the transpose stores phase-conflict-free; compute a-loads
// are broadcasts (all lanes of a half-warp share rb).
// Inner loop: 4 LDS.64 + 1 LDS.128 + 8 FFMA2 = 13 issue slots / 16 FMA cycles.
// ---------------------------------------------------------------------------
__global__ void __launch_bounds__(256) gemm_kernel(const float* __restrict__ x,
                                                   const float* __restrict__ W,
                                                   int n_rows)
{
    __shared__ __align__(16) float xs_dup[16][130];  // [kk][2*row {+0,+1}]
    __shared__ __align__(16) float ws[16][64];       // [kk][col]

    const int tid  = threadIdx.x;
    const int row0 = blockIdx.x * 64;

    // loader mapping
    const int lrow = tid >> 2;          // 0..63
    const int lkq  = (tid & 3) * 4;     // 0,4,8,12
    const int wk   = tid >> 4;          // 0..15
    const int wc   = (tid & 15) * 4;    // 0..60

    const int  grow = row0 + lrow;
    const bool rok  = grow < n_rows;
    const float* xptr = x + (size_t)(rok ? grow : 0) * DFEAT + lkq;
    const float* wptr = W + (size_t)wk * NOUT + wc;

    // compute mapping
    const int cb = (tid & 15) * 4;      // col base (4 cols)
    const int rb = (tid >> 4) * 4;      // row base (4 rows)

    // acc[r][p]: p=0 -> cols (cb,cb+1), p=1 -> cols (cb+2,cb+3), packed f32x2
    unsigned long long acc[4][2] = {};

    float4 xv = rok ? *(const float4*)xptr : make_float4(0.f, 0.f, 0.f, 0.f);
    float4 wv = *(const float4*)wptr;

    for (int kt = 0; kt < DFEAT / 16; ++kt) {
        // duplicated transpose store of x
        float2* p0 = (float2*)&xs_dup[lkq + 0][2 * lrow];
        float2* p1 = (float2*)&xs_dup[lkq + 1][2 * lrow];
        float2* p2 = (float2*)&xs_dup[lkq + 2][2 * lrow];
        float2* p3 = (float2*)&xs_dup[lkq + 3][2 * lrow];
        *p0 = make_float2(xv.x, xv.x);
        *p1 = make_float2(xv.y, xv.y);
        *p2 = make_float2(xv.z, xv.z);
        *p3 = make_float2(xv.w, xv.w);
        *(float4*)&ws[wk][wc] = wv;
        __syncthreads();

        if (kt < DFEAT / 16 - 1) {
            xv = rok ? *(const float4*)(xptr + (kt + 1) * 16)
                     : make_float4(0.f, 0.f, 0.f, 0.f);
            wv = *(const float4*)(wptr + (size_t)(kt + 1) * 16 * NOUT);
        }

#pragma unroll
        for (int kk = 0; kk < 16; ++kk) {
            unsigned long long a0 = *(const unsigned long long*)&xs_dup[kk][2 * rb + 0];
            unsigned long long a1 = *(const unsigned long long*)&xs_dup[kk][2 * rb + 2];
            unsigned long long a2 = *(const unsigned long long*)&xs_dup[kk][2 * rb + 4];
            unsigned long long a3 = *(const unsigned long long*)&xs_dup[kk][2 * rb + 6];
            ulonglong2 b = *(const ulonglong2*)&ws[kk][cb];  // (w0,w1),(w2,w3)
            asm("fma.rn.f32x2 %0,%1,%2,%0;" : "+l"(acc[0][0]) : "l"(a0), "l"(b.x));
            asm("fma.rn.f32x2 %0,%1,%2,%0;" : "+l"(acc[0][1]) : "l"(a0), "l"(b.y));
            asm("fma.rn.f32x2 %0,%1,%2,%0;" : "+l"(acc[1][0]) : "l"(a1), "l"(b.x));
            asm("fma.rn.f32x2 %0,%1,%2,%0;" : "+l"(acc[1][1]) : "l"(a1), "l"(b.y));
            asm("fma.rn.f32x2 %0,%1,%2,%0;" : "+l"(acc[2][0]) : "l"(a2), "l"(b.x));
            asm("fma.rn.f32x2 %0,%1,%2,%0;" : "+l"(acc[2][1]) : "l"(a2), "l"(b.y));
            asm("fma.rn.f32x2 %0,%1,%2,%0;" : "+l"(acc[3][0]) : "l"(a3), "l"(b.x));
            asm("fma.rn.f32x2 %0,%1,%2,%0;" : "+l"(acc[3][1]) : "l"(a3), "l"(b.y));
        }
        __syncthreads();
    }

#pragma unroll
    for (int r = 0; r < 4; ++r) {
        int gr = row0 + rb + r;
        if (gr < n_rows) {
            float2 lo = *reinterpret_cast<float2*>(&acc[r][0]);
            float2 hi = *reinterpret_cast<float2*>(&acc[r][1]);
            *(float4*)&g_h[(size_t)gr * NOUT + cb] = make_float4(lo.x, lo.y, hi.x, hi.y);
        }
    }
}

// ---------------------------------------------------------------------------
// Gather + fused softmax: one warp per dst node, lane owns 2 channels.
// Pairs fetched cooperatively (32 at a time), broadcast via shfl.
// 4-way unrolled inner loop for MLP on the h-row gathers.
// ---------------------------------------------------------------------------
__global__ void __launch_bounds__(256) gather_softmax_kernel(float* __restrict__ out,
                                                             int n_nodes)
{
    int node = blockIdx.x * 8 + (threadIdx.x >> 5);
    int lane = threadIdx.x & 31;
    if (node >= n_nodes) return;

    int start = __ldg(&g_start[node]);
    int end   = __ldg(&g_cursor[node]);   // cursor == row end after reorder

    float2 acc = make_float2(0.f, 0.f);

    for (int base = start; base < end; base += 32) {
        int idx = base + lane;
        uint2 pr = make_uint2(0u, 0u);
        if (idx < end) pr = __ldg(&g_pairs[idx]);
        int m = end - base; if (m > 32) m = 32;

        int j = 0;
        for (; j + 4 <= m; j += 4) {
#pragma unroll
            for (int u = 0; u < 4; ++u) {
                int   ss = __shfl_sync(0xffffffffu, (int)pr.x, j + u);
                float sw = __uint_as_float(__shfl_sync(0xffffffffu, pr.y, j + u));
                float2 hv = *(const float2*)(g_h + (size_t)ss * NOUT + (lane << 1));
                acc.x = fmaf(sw, hv.x, acc.x);
                acc.y = fmaf(sw, hv.y, acc.y);
            }
        }
        for (; j < m; ++j) {
            int   ss = __shfl_sync(0xffffffffu, (int)pr.x, j);
            float sw = __uint_as_float(__shfl_sync(0xffffffffu, pr.y, j));
            float2 hv = *(const float2*)(g_h + (size_t)ss * NOUT + (lane << 1));
            acc.x = fmaf(sw, hv.x, acc.x);
            acc.y = fmaf(sw, hv.y, acc.y);
        }
    }

    // fused softmax over the 64 channels held by this warp
    float mx = fmaxf(acc.x, acc.y);
#pragma unroll
    for (int o = 16; o > 0; o >>= 1)
        mx = fmaxf(mx, __shfl_xor_sync(0xffffffffu, mx, o));

    float e0 = __expf(acc.x - mx);
    float e1 = __expf(acc.y - mx);
    float s = e0 + e1;
#pragma unroll
    for (int o = 16; o > 0; o >>= 1)
        s += __shfl_xor_sync(0xffffffffu, s, o);

    float inv = 1.0f / s;
    *(float2*)&out[(size_t)node * NOUT + (lane << 1)] = make_float2(e0 * inv, e1 * inv);
}

// ---------------------------------------------------------------------------
// Launch.  Input order per metadata: x, edge_src, edge_dst, edge_w, W.
// ---------------------------------------------------------------------------
extern "C" void kernel_launch(void* const* d_in, const int* in_sizes, int n_in,
                              void* d_out, int out_size)
{
    const float* x    = (const float*)d_in[0];
    const int*   esrc = (const int*)  d_in[1];
    const int*   edst = (const int*)  d_in[2];
    const float* ew   = (const float*)d_in[3];
    const float* W    = (const float*)d_in[4];
    float*       out  = (float*)d_out;

    const int n_nodes = in_sizes[0] / DFEAT;
    const int n_edges = in_sizes[1];
    const int eblk    = (n_edges + 255) / 256;
    const int ntiles  = (n_nodes + 1023) / 1024;   // scan tiles of 1024

    // CSR build (dst-grouped)
    zero_cnt_kernel<<<(NPAD / 4 + 255) / 256, 256>>>();
    hist_kernel<<<eblk, 256>>>(edst, n_edges);
    scan_reduce_kernel<<<ntiles, 256>>>();
    scan_mid_kernel<<<1, 128>>>(ntiles);
    scan_scatter_kernel<<<ntiles, 256>>>();
    reorder_kernel<<<eblk, 256>>>(esrc, edst, ew, n_edges);

    // h = x @ W   (h lands in L2 right before the gather consumes it)
    gemm_kernel<<<(n_nodes + 63) / 64, 256>>>(x, W, n_nodes);

    // agg + softmax fused
    gather_softmax_kernel<<<(n_nodes + 7) / 8, 256>>>(out, n_nodes);
}

// round 5
// speedup vs baseline: 1.4625x; 1.4625x over previous
#include <cuda_runtime.h>
#include <cuda_bf16.h>
#include <mma.h>
#include <cstdint>

using namespace nvcuda;

// Problem constants (fixed by dataset)
#define DFEAT 512
#define NOUT  64
#define MAXN  100032          // N_NODES rounded up to 64
#define NPAD  102400          // node arrays padded to 1024*100 for scan tiles
#define MAXE  1600000
#define NBLK_SCAN 100         // NPAD / 1024

// Static device scratch (no runtime allocation allowed)
__device__ float        g_h[(size_t)MAXN * NOUT];  // projected features (25.6 MB)
__device__ uint2        g_pairs[MAXE];             // (src, w-bits) grouped by dst
__device__ int          g_cnt[NPAD];               // per-dst degree
__device__ int          g_start[NPAD];             // CSR row start
__device__ int          g_cursor[NPAD];            // fill cursor == row end after reorder
__device__ unsigned int g_tilestate[NBLK_SCAN];    // lookback state: flag<<30 | sum

// ---------------------------------------------------------------------------
// Step 1: zero histogram + scan state (graph is replayed -> must reset state!)
// ---------------------------------------------------------------------------
__global__ void zero_cnt_kernel() {
    int i = blockIdx.x * blockDim.x + threadIdx.x;
    if (i < NPAD / 4) ((int4*)g_cnt)[i] = make_int4(0, 0, 0, 0);
    if (i < NBLK_SCAN) g_tilestate[i] = 0u;
}

// ---------------------------------------------------------------------------
// Step 2: degree histogram over dst
// ---------------------------------------------------------------------------
__global__ void hist_kernel(const int* __restrict__ edst, int n_edges) {
    int e = blockIdx.x * blockDim.x + threadIdx.x;
    if (e < n_edges) atomicAdd(&g_cnt[__ldg(&edst[e])], 1);
}

// ---------------------------------------------------------------------------
// Step 3: single-pass exclusive scan (decoupled lookback), 1024 nodes / block.
// Writes g_start (row starts) and g_cursor (fill cursors).
// ---------------------------------------------------------------------------
__global__ void __launch_bounds__(256) scan_onepass_kernel() {
    const int b   = blockIdx.x;
    const int tid = threadIdx.x;
    const int idx = b * 1024 + tid * 4;

    int4 c = *(const int4*)&g_cnt[idx];
    int t = c.x + c.y + c.z + c.w;

    // warp inclusive scan of t
    int incl = t;
#pragma unroll
    for (int o = 1; o < 32; o <<= 1) {
        int u = __shfl_up_sync(0xffffffffu, incl, o);
        if ((tid & 31) >= o) incl += u;
    }
    __shared__ int wsum[8];
    __shared__ int s_excl;
    if ((tid & 31) == 31) wsum[tid >> 5] = incl;
    __syncthreads();

    const int wid = tid >> 5;
    int off = 0, agg = 0;
#pragma unroll
    for (int i = 0; i < 8; ++i) {
        int v = wsum[i];
        if (i < wid) off += v;
        agg += v;
    }

    if (tid == 0) {
        if (b == 0) {
            atomicExch(&g_tilestate[0], (2u << 30) | (unsigned)agg);
            s_excl = 0;
        } else {
            // publish aggregate, then look back
            atomicExch(&g_tilestate[b], (1u << 30) | (unsigned)agg);
            int run = 0, p = b - 1;
            while (true) {
                unsigned s;
                do { s = atomicAdd(&g_tilestate[p], 0u); } while ((s >> 30) == 0u);
                run += (int)(s & 0x3fffffffu);
                if ((s >> 30) == 2u) break;
                --p;
            }
            atomicExch(&g_tilestate[b], (2u << 30) | (unsigned)(run + agg));
            s_excl = run;
        }
    }
    __syncthreads();

    int s0 = s_excl + (incl - t) + off;     // exclusive prefix of element idx
    int4 st;
    st.x = s0; st.y = s0 + c.x; st.z = st.y + c.y; st.w = st.z + c.z;
    *(int4*)&g_start[idx]  = st;
    *(int4*)&g_cursor[idx] = st;
}

// ---------------------------------------------------------------------------
// Step 4 (launch slot 4 -> ncu-captured): GEMM h = x @ W via split-bf16 HMMA.
// x,W split hi/lo bf16 in smem; acc fp32: h = xh*Wh + xh*Wl + xl*Wh.
// Block: 256 thr, tile 64 rows x 64 cols, BK=16, 8 warps in 4x2 layout,
// each warp owns a 16x32 output tile (two 16x16 wmma accumulators).
// ---------------------------------------------------------------------------
__global__ void __launch_bounds__(256) gemm_kernel(const float* __restrict__ x,
                                                   const float* __restrict__ W,
                                                   int n_rows)
{
    __shared__ __align__(16) __nv_bfloat16 xs_hi[64][24];
    __shared__ __align__(16) __nv_bfloat16 xs_lo[64][24];
    __shared__ __align__(16) __nv_bfloat16 ws_hi[16][72];
    __shared__ __align__(16) __nv_bfloat16 ws_lo[16][72];

    const int tid  = threadIdx.x;
    const int row0 = blockIdx.x * 64;

    // x loader: thread -> (row = tid>>2, 4 cols at (tid&3)*4)
    const int lr = tid >> 2;
    const int lq = (tid & 3) * 4;
    int grow = row0 + lr;
    if (grow >= n_rows) grow = n_rows - 1;          // clamp (dup rows, never read)
    const float* xptr = x + (size_t)grow * DFEAT + lq;

    // W loader: thread -> (k row = tid>>4, 4 cols at (tid&15)*4)
    const int wr  = tid >> 4;
    const int wc4 = (tid & 15) * 4;
    const float* wptr = W + (size_t)wr * NOUT + wc4;

    const int wid    = tid >> 5;
    const int warp_r = (wid >> 1) * 16;   // 0,16,32,48
    const int warp_c = (wid & 1) * 32;    // 0,32

    wmma::fragment<wmma::accumulator, 16, 16, 16, float> acc0, acc1;
    wmma::fill_fragment(acc0, 0.0f);
    wmma::fill_fragment(acc1, 0.0f);

    float4 xv = *(const float4*)xptr;
    float4 wv = *(const float4*)wptr;

    for (int kt = 0; kt < DFEAT / 16; ++kt) {
        // split-convert and stage
        {
            float a[4] = {xv.x, xv.y, xv.z, xv.w};
#pragma unroll
            for (int i = 0; i < 4; ++i) {
                __nv_bfloat16 h = __float2bfloat16_rn(a[i]);
                xs_hi[lr][lq + i] = h;
                xs_lo[lr][lq + i] = __float2bfloat16_rn(a[i] - __bfloat162float(h));
            }
            float b[4] = {wv.x, wv.y, wv.z, wv.w};
#pragma unroll
            for (int i = 0; i < 4; ++i) {
                __nv_bfloat16 h = __float2bfloat16_rn(b[i]);
                ws_hi[wr][wc4 + i] = h;
                ws_lo[wr][wc4 + i] = __float2bfloat16_rn(b[i] - __bfloat162float(h));
            }
        }
        __syncthreads();

        if (kt < DFEAT / 16 - 1) {   // prefetch next tile
            xv = *(const float4*)(xptr + (kt + 1) * 16);
            wv = *(const float4*)(wptr + (size_t)(kt + 1) * 16 * NOUT);
        }

        wmma::fragment<wmma::matrix_a, 16, 16, 16, __nv_bfloat16, wmma::row_major> a_hi, a_lo;
        wmma::fragment<wmma::matrix_b, 16, 16, 16, __nv_bfloat16, wmma::row_major> b_hi, b_lo;
        wmma::load_matrix_sync(a_hi, &xs_hi[warp_r][0], 24);
        wmma::load_matrix_sync(a_lo, &xs_lo[warp_r][0], 24);

        wmma::load_matrix_sync(b_hi, &ws_hi[0][warp_c], 72);
        wmma::load_matrix_sync(b_lo, &ws_lo[0][warp_c], 72);
        wmma::mma_sync(acc0, a_hi, b_hi, acc0);
        wmma::mma_sync(acc0, a_hi, b_lo, acc0);
        wmma::mma_sync(acc0, a_lo, b_hi, acc0);

        wmma::load_matrix_sync(b_hi, &ws_hi[0][warp_c + 16], 72);
        wmma::load_matrix_sync(b_lo, &ws_lo[0][warp_c + 16], 72);
        wmma::mma_sync(acc1, a_hi, b_hi, acc1);
        wmma::mma_sync(acc1, a_hi, b_lo, acc1);
        wmma::mma_sync(acc1, a_lo, b_hi, acc1);

        __syncthreads();
    }

    // g_h is padded to MAXN rows; full-tile stores stay in bounds.
    float* outp = g_h + (size_t)(row0 + warp_r) * NOUT + warp_c;
    wmma::store_matrix_sync(outp,      acc0, NOUT, wmma::mem_row_major);
    wmma::store_matrix_sync(outp + 16, acc1, NOUT, wmma::mem_row_major);
}

// ---------------------------------------------------------------------------
// Step 5: reorder edges into dst-grouped (src, w) pairs.
// ---------------------------------------------------------------------------
__global__ void __launch_bounds__(256) reorder_kernel(const int*   __restrict__ esrc,
                                                      const int*   __restrict__ edst,
                                                      const float* __restrict__ ew,
                                                      int n_edges)
{
    int e = blockIdx.x * blockDim.x + threadIdx.x;
    if (e >= n_edges) return;
    int d = __ldg(&edst[e]);
    int pos = atomicAdd(&g_cursor[d], 1);
    g_pairs[pos] = make_uint2((unsigned)__ldg(&esrc[e]), __float_as_uint(__ldg(&ew[e])));
}

// ---------------------------------------------------------------------------
// Step 6: gather + fused softmax. One warp per dst node, lane owns 2 channels.
// Cooperative 32-wide pair fetch + shfl broadcast; 8-way unroll for MLP.
// ---------------------------------------------------------------------------
__global__ void __launch_bounds__(256) gather_softmax_kernel(float* __restrict__ out,
                                                             int n_nodes)
{
    int node = blockIdx.x * 8 + (threadIdx.x >> 5);
    int lane = threadIdx.x & 31;
    if (node >= n_nodes) return;

    int start = __ldg(&g_start[node]);
    int end   = __ldg(&g_cursor[node]);

    float2 acc = make_float2(0.f, 0.f);

    for (int base = start; base < end; base += 32) {
        int idx = base + lane;
        uint2 pr = make_uint2(0u, 0u);
        if (idx < end) pr = __ldg(&g_pairs[idx]);
        int m = end - base; if (m > 32) m = 32;

        int j = 0;
        for (; j + 8 <= m; j += 8) {
#pragma unroll
            for (int u = 0; u < 8; ++u) {
                int   ss = __shfl_sync(0xffffffffu, (int)pr.x, j + u);
                float sw = __uint_as_float(__shfl_sync(0xffffffffu, pr.y, j + u));
                float2 hv = *(const float2*)(g_h + (size_t)ss * NOUT + (lane << 1));
                acc.x = fmaf(sw, hv.x, acc.x);
                acc.y = fmaf(sw, hv.y, acc.y);
            }
        }
        for (; j < m; ++j) {
            int   ss = __shfl_sync(0xffffffffu, (int)pr.x, j);
            float sw = __uint_as_float(__shfl_sync(0xffffffffu, pr.y, j));
            float2 hv = *(const float2*)(g_h + (size_t)ss * NOUT + (lane << 1));
            acc.x = fmaf(sw, hv.x, acc.x);
            acc.y = fmaf(sw, hv.y, acc.y);
        }
    }

    // fused softmax over the 64 channels held by this warp
    float mx = fmaxf(acc.x, acc.y);
#pragma unroll
    for (int o = 16; o > 0; o >>= 1)
        mx = fmaxf(mx, __shfl_xor_sync(0xffffffffu, mx, o));

    float e0 = __expf(acc.x - mx);
    float e1 = __expf(acc.y - mx);
    float s = e0 + e1;
#pragma unroll
    for (int o = 16; o > 0; o >>= 1)
        s += __shfl_xor_sync(0xffffffffu, s, o);

    float inv = 1.0f / s;
    *(float2*)&out[(size_t)node * NOUT + (lane << 1)] = make_float2(e0 * inv, e1 * inv);
}

// ---------------------------------------------------------------------------
// Launch. Input order per metadata: x, edge_src, edge_dst, edge_w, W.
// GEMM deliberately placed as the 4th launch (ncu captures launch #4).
// ---------------------------------------------------------------------------
extern "C" void kernel_launch(void* const* d_in, const int* in_sizes, int n_in,
                              void* d_out, int out_size)
{
    const float* x    = (const float*)d_in[0];
    const int*   esrc = (const int*)  d_in[1];
    const int*   edst = (const int*)  d_in[2];
    const float* ew   = (const float*)d_in[3];
    const float* W    = (const float*)d_in[4];
    float*       out  = (float*)d_out;

    const int n_nodes = in_sizes[0] / DFEAT;
    const int n_edges = in_sizes[1];
    const int eblk    = (n_edges + 255) / 256;
    const int ntiles  = (n_nodes + 1023) / 1024;

    zero_cnt_kernel<<<(NPAD / 4 + 255) / 256, 256>>>();                  // 1
    hist_kernel<<<eblk, 256>>>(edst, n_edges);                           // 2
    scan_onepass_kernel<<<ntiles, 256>>>();                              // 3
    gemm_kernel<<<(n_nodes + 63) / 64, 256>>>(x, W, n_nodes);            // 4 (profiled)
    reorder_kernel<<<eblk, 256>>>(esrc, edst, ew, n_edges);              // 5
    gather_softmax_kernel<<<(n_nodes + 7) / 8, 256>>>(out, n_nodes);     // 6
}